// round 3
// baseline (speedup 1.0000x reference)
#include <cuda_runtime.h>

#define NN    2048
#define DIN   128
#define HH    256
#define DEMB  64
#define NSTRIP 4
#define STRIPJ (NN / NSTRIP)   // 512
#define BI    32
#define BJ    64

// -------- device scratch (no allocations allowed) --------
__device__ float g_emb[NN * DEMB];          // 512 KB
__device__ float g_sq[NN];                  // 8 KB
__device__ float g_xlast[NN * DIN];         // 1 MB
__device__ float g_ypart[NSTRIP * NN * DIN];// 4 MB
__device__ float g_degpart[NSTRIP * NN];    // 32 KB

__device__ __forceinline__ float sigmoidf(float z) {
    return 1.0f / (1.0f + __expf(-z));
}

// ============================================================
// Kernel A: out_x = relu(x@W0+b0); emb = relu(out_x@W1+b1);
//           sq = rowsum(emb^2); x_last = x@W2+b2
// One block = 16 rows, 256 threads.
// ============================================================
__global__ void __launch_bounds__(256) kA(
    const float* __restrict__ x,
    const float* __restrict__ W0, const float* __restrict__ b0,
    const float* __restrict__ W1, const float* __restrict__ b1,
    const float* __restrict__ W2, const float* __restrict__ b2)
{
    __shared__ float xs[16][DIN];        // 8 KB
    __shared__ float oxs[16][HH];        // 16 KB
    __shared__ float embs[16][DEMB + 1]; // padded vs bank conflicts

    const int t = threadIdx.x;
    const int row0 = blockIdx.x * 16;

    // load 16 x-rows
    #pragma unroll
    for (int idx = t; idx < 16 * DIN; idx += 256)
        xs[idx / DIN][idx % DIN] = x[row0 * DIN + idx];
    __syncthreads();

    // ---- stage 1: out_x tile [16, 256]; thread t owns column h=t ----
    {
        float acc[16];
        #pragma unroll
        for (int r = 0; r < 16; r++) acc[r] = 0.f;
        const int h = t;
        for (int k = 0; k < DIN; k++) {
            const float w = W0[k * HH + h];
            #pragma unroll
            for (int r = 0; r < 16; r++) acc[r] = fmaf(xs[r][k], w, acc[r]);
        }
        const float bb = b0[h];
        #pragma unroll
        for (int r = 0; r < 16; r++) oxs[r][h] = fmaxf(acc[r] + bb, 0.f);
    }
    __syncthreads();

    // ---- stage 2: emb tile [16, 64]; 4 row-groups x 64 columns ----
    {
        const int e  = t & 63;
        const int rg = t >> 6;             // 0..3 -> rows 4*rg..4*rg+3
        float acc[4] = {0.f, 0.f, 0.f, 0.f};
        for (int h = 0; h < HH; h++) {
            const float w = W1[h * DEMB + e];
            #pragma unroll
            for (int rr = 0; rr < 4; rr++)
                acc[rr] = fmaf(oxs[4 * rg + rr][h], w, acc[rr]);
        }
        const float bb = b1[e];
        #pragma unroll
        for (int rr = 0; rr < 4; rr++) {
            const float v = fmaxf(acc[rr] + bb, 0.f);
            embs[4 * rg + rr][e] = v;
            g_emb[(row0 + 4 * rg + rr) * DEMB + e] = v;
        }
    }

    // ---- stage 3: x_last tile [16, 128]; 2 row-groups x 128 columns ----
    {
        const int d  = t & 127;
        const int rg = t >> 7;             // 0..1 -> rows 8*rg..8*rg+7
        float acc[8];
        #pragma unroll
        for (int rr = 0; rr < 8; rr++) acc[rr] = 0.f;
        for (int k = 0; k < DIN; k++) {
            const float w = W2[k * DIN + d];
            #pragma unroll
            for (int rr = 0; rr < 8; rr++)
                acc[rr] = fmaf(xs[8 * rg + rr][k], w, acc[rr]);
        }
        const float bb = b2[d];
        #pragma unroll
        for (int rr = 0; rr < 8; rr++)
            g_xlast[(row0 + 8 * rg + rr) * DIN + d] = acc[rr] + bb;
    }
    __syncthreads();

    // ---- sq ----
    if (t < 16) {
        float s = 0.f;
        #pragma unroll
        for (int e = 0; e < DEMB; e++) { const float v = embs[t][e]; s = fmaf(v, v, s); }
        g_sq[row0 + t] = s;
    }
}

// ============================================================
// Kernel B: per block — 32 i-rows x 512 j-cols strip of A.
//  GEMM1: G = embI @ embJ^T   (k-major smem operands)
//  epilogue: A = sigmoid(c1*(2G - sqi - sqj) + c2) + eye -> adj_out
//  GEMM2: y += A_tile @ x_last_chunk   (register accumulators)
// Writes per-strip partials of deg and y (deterministic, no atomics).
// ============================================================
__global__ void __launch_bounds__(256) kB(
    const float* __restrict__ tempp,
    const float* __restrict__ thetap,
    float* __restrict__ adj_out)
{
    extern __shared__ float sm[];
    float* embIs = sm;                    // [64][33]  (k-major, padded)
    float* embJs = embIs + 64 * 33;       // [64][65]  (k-major, padded)
    float* xls   = embJs + 64 * 65;       // [64][128] (j-major)
    float* sqJs  = xls + 64 * DIN;        // [64]
    float* As    = sqJs + 64;             // [32][68]  (padded, 16B-alignable)
    float* degsh = As + 32 * 68;          // [32][16]

    const int t  = threadIdx.x;
    const int s  = blockIdx.x;            // strip
    const int i0 = blockIdx.y * BI;
    const int jstart = s * STRIPJ;

    const float c1 = 1.0f + *tempp;
    const float c2 = 5.0f + *thetap;

    // stage embI transposed (k-major)
    #pragma unroll
    for (int idx = t; idx < BI * DEMB; idx += 256) {
        const int k = idx & 63, r = idx >> 6;
        embIs[k * 33 + r] = g_emb[(i0 + r) * DEMB + k];
    }

    // GEMM1 thread coords: 2 rows x 4 cols
    const int c0 = (t & 15) * 4;
    const int r0 = (t >> 4) * 2;
    const float sqI0 = g_sq[i0 + r0];
    const float sqI1 = g_sq[i0 + r0 + 1];
    float degAcc0 = 0.f, degAcc1 = 0.f;

    // GEMM2 thread coords: 1 row x 16 cols
    const int yrow = t >> 3;
    const int ycol = (t & 7) * 16;
    float yacc[16];
    #pragma unroll
    for (int q = 0; q < 16; q++) yacc[q] = 0.f;

    for (int cj = 0; cj < STRIPJ / BJ; cj++) {
        const int jb = jstart + cj * BJ;
        __syncthreads();   // previous-iter readers done before overwrite

        // stage embJ transposed
        #pragma unroll
        for (int idx = t; idx < BJ * DEMB; idx += 256) {
            const int k = idx & 63, jl = idx >> 6;
            embJs[k * 65 + jl] = g_emb[(jb + jl) * DEMB + k];
        }
        if (t < BJ) sqJs[t] = g_sq[jb + t];
        // stage x_last chunk [64][128] via float4
        {
            const float4* src = (const float4*)(g_xlast + (size_t)jb * DIN);
            float4* dst = (float4*)xls;
            #pragma unroll
            for (int idx = t; idx < BJ * DIN / 4; idx += 256) dst[idx] = src[idx];
        }
        __syncthreads();

        // ---- GEMM1: G tile, 2x4 per thread over k=64 ----
        float a00 = 0.f, a01 = 0.f, a02 = 0.f, a03 = 0.f;
        float a10 = 0.f, a11 = 0.f, a12 = 0.f, a13 = 0.f;
        #pragma unroll 4
        for (int k = 0; k < DEMB; k++) {
            const float ai0 = embIs[k * 33 + r0];
            const float ai1 = embIs[k * 33 + r0 + 1];
            const float bj0 = embJs[k * 65 + c0 + 0];
            const float bj1 = embJs[k * 65 + c0 + 1];
            const float bj2 = embJs[k * 65 + c0 + 2];
            const float bj3 = embJs[k * 65 + c0 + 3];
            a00 = fmaf(ai0, bj0, a00); a01 = fmaf(ai0, bj1, a01);
            a02 = fmaf(ai0, bj2, a02); a03 = fmaf(ai0, bj3, a03);
            a10 = fmaf(ai1, bj0, a10); a11 = fmaf(ai1, bj1, a11);
            a12 = fmaf(ai1, bj2, a12); a13 = fmaf(ai1, bj3, a13);
        }

        // ---- epilogue: sigmoid + eye, write adj, stash A tile, deg ----
        {
            const float sj0 = sqJs[c0 + 0], sj1 = sqJs[c0 + 1];
            const float sj2 = sqJs[c0 + 2], sj3 = sqJs[c0 + 3];
            const int gi0 = i0 + r0;
            const int gj0 = jb + c0;

            float4 w0, w1;
            w0.x = sigmoidf(fmaf(c1, 2.f * a00 - sqI0 - sj0, c2));
            w0.y = sigmoidf(fmaf(c1, 2.f * a01 - sqI0 - sj1, c2));
            w0.z = sigmoidf(fmaf(c1, 2.f * a02 - sqI0 - sj2, c2));
            w0.w = sigmoidf(fmaf(c1, 2.f * a03 - sqI0 - sj3, c2));
            w1.x = sigmoidf(fmaf(c1, 2.f * a10 - sqI1 - sj0, c2));
            w1.y = sigmoidf(fmaf(c1, 2.f * a11 - sqI1 - sj1, c2));
            w1.z = sigmoidf(fmaf(c1, 2.f * a12 - sqI1 - sj2, c2));
            w1.w = sigmoidf(fmaf(c1, 2.f * a13 - sqI1 - sj3, c2));

            // identity on the diagonal
            const int d0 = gj0 - gi0;          // diag if col offset == 0..3
            if (d0 == 0)  w0.x += 1.f;
            if (d0 == -1) w0.y += 1.f;
            if (d0 == -2) w0.z += 1.f;
            if (d0 == -3) w0.w += 1.f;
            const int d1 = gj0 - (gi0 + 1);
            if (d1 == 0)  w1.x += 1.f;
            if (d1 == -1) w1.y += 1.f;
            if (d1 == -2) w1.z += 1.f;
            if (d1 == -3) w1.w += 1.f;

            degAcc0 += (w0.x + w0.y) + (w0.z + w0.w);
            degAcc1 += (w1.x + w1.y) + (w1.z + w1.w);

            *(float4*)(adj_out + (size_t)gi0 * NN + gj0)       = w0;
            *(float4*)(adj_out + (size_t)(gi0 + 1) * NN + gj0) = w1;

            *(float4*)(As + r0 * 68 + c0)       = w0;
            *(float4*)(As + (r0 + 1) * 68 + c0) = w1;
        }
        __syncthreads();

        // ---- GEMM2: y[32][128] += A[32][64] @ xls[64][128] ----
        for (int c = 0; c < BJ; c++) {
            const float a = As[yrow * 68 + c];
            const float4* xr = (const float4*)(xls + c * DIN + ycol);
            const float4 x0 = xr[0], x1 = xr[1], x2 = xr[2], x3 = xr[3];
            yacc[0]  = fmaf(a, x0.x, yacc[0]);  yacc[1]  = fmaf(a, x0.y, yacc[1]);
            yacc[2]  = fmaf(a, x0.z, yacc[2]);  yacc[3]  = fmaf(a, x0.w, yacc[3]);
            yacc[4]  = fmaf(a, x1.x, yacc[4]);  yacc[5]  = fmaf(a, x1.y, yacc[5]);
            yacc[6]  = fmaf(a, x1.z, yacc[6]);  yacc[7]  = fmaf(a, x1.w, yacc[7]);
            yacc[8]  = fmaf(a, x2.x, yacc[8]);  yacc[9]  = fmaf(a, x2.y, yacc[9]);
            yacc[10] = fmaf(a, x2.z, yacc[10]); yacc[11] = fmaf(a, x2.w, yacc[11]);
            yacc[12] = fmaf(a, x3.x, yacc[12]); yacc[13] = fmaf(a, x3.y, yacc[13]);
            yacc[14] = fmaf(a, x3.z, yacc[14]); yacc[15] = fmaf(a, x3.w, yacc[15]);
        }
    }

    // write y partials
    {
        float4* yp = (float4*)(g_ypart + ((size_t)s * NN + i0 + yrow) * DIN + ycol);
        yp[0] = make_float4(yacc[0],  yacc[1],  yacc[2],  yacc[3]);
        yp[1] = make_float4(yacc[4],  yacc[5],  yacc[6],  yacc[7]);
        yp[2] = make_float4(yacc[8],  yacc[9],  yacc[10], yacc[11]);
        yp[3] = make_float4(yacc[12], yacc[13], yacc[14], yacc[15]);
    }

    // deg reduction (deterministic)
    degsh[r0 * 16 + (t & 15)]       = degAcc0;
    degsh[(r0 + 1) * 16 + (t & 15)] = degAcc1;
    __syncthreads();
    if (t < BI) {
        float sdeg = 0.f;
        #pragma unroll
        for (int g = 0; g < 16; g++) sdeg += degsh[t * 16 + g];
        g_degpart[s * NN + i0 + t] = sdeg;
    }
}

// ============================================================
// Kernel C: out = relu( (sum_s y_part) / (sum_s deg_part) )
// ============================================================
__global__ void __launch_bounds__(256) kC(float* __restrict__ out)
{
    const int idx = blockIdx.x * 256 + threadIdx.x;  // < N*DIN
    const int i = idx >> 7;
    const int d = idx & 127;
    float deg = 0.f;
    #pragma unroll
    for (int s = 0; s < NSTRIP; s++) deg += g_degpart[s * NN + i];
    float y = 0.f;
    #pragma unroll
    for (int s = 0; s < NSTRIP; s++)
        y += g_ypart[((size_t)s * NN + i) * DIN + d];
    out[idx] = fmaxf(y / deg, 0.f);
}

// ============================================================
extern "C" void kernel_launch(void* const* d_in, const int* in_sizes, int n_in,
                              void* d_out, int out_size)
{
    const float* x     = (const float*)d_in[0];
    // d_in[1] = adj : unused (only its shape matters in the reference)
    const float* W0    = (const float*)d_in[2];
    const float* b0    = (const float*)d_in[3];
    const float* W1    = (const float*)d_in[4];
    const float* b1    = (const float*)d_in[5];
    const float* W2    = (const float*)d_in[6];
    const float* b2    = (const float*)d_in[7];
    const float* temp  = (const float*)d_in[8];
    const float* theta = (const float*)d_in[9];

    float* out     = (float*)d_out;          // [N, DIN] first
    float* adj_out = out + NN * DIN;         // then [N*N] adjacency

    kA<<<NN / 16, 256>>>(x, W0, b0, W1, b1, W2, b2);

    const int smemB = (64 * 33 + 64 * 65 + 64 * DIN + 64 + 32 * 68 + 32 * 16) * 4;
    cudaFuncSetAttribute(kB, cudaFuncAttributeMaxDynamicSharedMemorySize, smemB);
    dim3 gB(NSTRIP, NN / BI);
    kB<<<gB, 256, smemB>>>(temp, theta, adj_out);

    kC<<<NN * DIN / 256, 256>>>(out);
}